// round 1
// baseline (speedup 1.0000x reference)
#include <cuda_runtime.h>
#include <math.h>

#define BATCH 8
#define DIM   512
#define HEADS 8
#define DH    64
#define LSEQ  4096
#define F3    1536            // 3 * HEADS * DH
#define SCALE 0.125f          // DH^-0.5
#define NSPLIT 16

// ---------------- scratch (device globals; no allocation allowed) ----------
__device__ float g_qkv[(size_t)BATCH * F3 * LSEQ];                  // 201 MB
__device__ float g_ctxp[(size_t)BATCH * HEADS * NSPLIT * DH * DH];  // 16.8 MB
__device__ float g_ctx[(size_t)BATCH * HEADS * DH * DH];            // 1 MB
__device__ float g_wctxT[(size_t)BATCH * DIM * DIM];                // 8 MB

// ---------------------------------------------------------------------------
// Generic tiled GEMM:  C[m,n] = sum_k A[k,m] * B[k,n] (+ bias[m])
// A is K-major (K x M, row stride lda), B is K-major (K x N, row stride ldb).
// BM=BN=64, BK=16, 256 threads, 4x4 register blocking, vectorized smem.
// ---------------------------------------------------------------------------
__global__ __launch_bounds__(256) void gemm_kkm(
    const float* __restrict__ A, const float* __restrict__ Bm,
    float* __restrict__ C,
    int M, int N, int K, int lda, int ldb, int ldc,
    long sA, long sB, long sC,
    const float* __restrict__ bias)
{
    const int bz = blockIdx.z;
    A  += (long)bz * sA;
    Bm += (long)bz * sB;
    C  += (long)bz * sC;

    const int m0 = blockIdx.y * 64;
    const int n0 = blockIdx.x * 64;

    __shared__ float As[16][64];
    __shared__ float Bs[16][64];

    const int tid = threadIdx.x;
    const int tx = tid & 15;        // n direction
    const int ty = tid >> 4;        // m direction
    const int lm = tid & 63;        // load column
    const int lk = tid >> 6;        // load row base (0..3)

    float acc[4][4] = {};

    for (int k0 = 0; k0 < K; k0 += 16) {
#pragma unroll
        for (int i = 0; i < 4; i++) {
            const int kr = lk + i * 4;
            As[kr][lm] = A[(long)(k0 + kr) * lda + (m0 + lm)];
            Bs[kr][lm] = Bm[(long)(k0 + kr) * ldb + (n0 + lm)];
        }
        __syncthreads();

#pragma unroll
        for (int kk = 0; kk < 16; kk++) {
            const float4 a4 = *reinterpret_cast<const float4*>(&As[kk][ty * 4]);
            const float4 b4 = *reinterpret_cast<const float4*>(&Bs[kk][tx * 4]);
            const float a[4] = {a4.x, a4.y, a4.z, a4.w};
            const float b[4] = {b4.x, b4.y, b4.z, b4.w};
#pragma unroll
            for (int i = 0; i < 4; i++)
#pragma unroll
                for (int j = 0; j < 4; j++)
                    acc[i][j] = fmaf(a[i], b[j], acc[i][j]);
        }
        __syncthreads();
    }

#pragma unroll
    for (int i = 0; i < 4; i++) {
        const int m = m0 + ty * 4 + i;
        const float bv = bias ? bias[m] : 0.0f;
        float4 o;
        o.x = acc[i][0] + bv;
        o.y = acc[i][1] + bv;
        o.z = acc[i][2] + bv;
        o.w = acc[i][3] + bv;
        *reinterpret_cast<float4*>(&C[(long)m * ldc + n0 + tx * 4]) = o;
    }
}

// ---------------------------------------------------------------------------
// Softmax over L for the K third of qkv (rows [DIM, 2*DIM) per batch), in place.
// One block (256 threads) per row of 4096; row cached in registers (16 f/thr).
// ---------------------------------------------------------------------------
__global__ __launch_bounds__(256) void softmax_rows()
{
    const int row = blockIdx.x;           // 0 .. BATCH*DIM-1
    const int b = row / DIM;
    const int r = row % DIM;
    float* p = g_qkv + (long)b * F3 * LSEQ + (long)(DIM + r) * LSEQ;

    const int tid = threadIdx.x;
    float4 v[4];
    float mx = -1e30f;
#pragma unroll
    for (int i = 0; i < 4; i++) {
        v[i] = reinterpret_cast<float4*>(p)[tid + i * 256];
        mx = fmaxf(mx, fmaxf(fmaxf(v[i].x, v[i].y), fmaxf(v[i].z, v[i].w)));
    }

    __shared__ float red[8];
#pragma unroll
    for (int o = 16; o; o >>= 1) mx = fmaxf(mx, __shfl_xor_sync(~0u, mx, o));
    if ((tid & 31) == 0) red[tid >> 5] = mx;
    __syncthreads();
    mx = red[0];
#pragma unroll
    for (int i = 1; i < 8; i++) mx = fmaxf(mx, red[i]);
    __syncthreads();

    float s = 0.0f;
#pragma unroll
    for (int i = 0; i < 4; i++) {
        v[i].x = expf(v[i].x - mx);
        v[i].y = expf(v[i].y - mx);
        v[i].z = expf(v[i].z - mx);
        v[i].w = expf(v[i].w - mx);
        s += v[i].x + v[i].y + v[i].z + v[i].w;
    }
#pragma unroll
    for (int o = 16; o; o >>= 1) s += __shfl_xor_sync(~0u, s, o);
    if ((tid & 31) == 0) red[tid >> 5] = s;
    __syncthreads();
    s = red[0];
#pragma unroll
    for (int i = 1; i < 8; i++) s += red[i];
    const float inv = 1.0f / s;

#pragma unroll
    for (int i = 0; i < 4; i++) {
        v[i].x *= inv; v[i].y *= inv; v[i].z *= inv; v[i].w *= inv;
        reinterpret_cast<float4*>(p)[tid + i * 256] = v[i];
    }
}

// ---------------------------------------------------------------------------
// ctx partials: per (b,h,split): partial[d,e] = sum_{n in slice} Ksm[d,n]*V[e,n]
// grid (64, NSPLIT). Deterministic (no atomics) — reduced by ctx_reduce.
// ---------------------------------------------------------------------------
__global__ __launch_bounds__(256) void ctx_partial()
{
    const int bh = blockIdx.x;                 // 0..63
    const int split = blockIdx.y;              // 0..NSPLIT-1
    const int b = bh / HEADS, h = bh % HEADS;
    const float* Kp = g_qkv + (long)b * F3 * LSEQ + (long)(DIM + h * DH) * LSEQ;
    const float* Vp = g_qkv + (long)b * F3 * LSEQ + (long)(2 * DIM + h * DH) * LSEQ;
    const int n0 = split * (LSEQ / NSPLIT);    // 256 per slice

    __shared__ float Ks[64][33];
    __shared__ float Vs[64][33];

    const int tid = threadIdx.x;
    const int tx = tid & 15, ty = tid >> 4;
    const int ln = tid & 31, lr = tid >> 5;    // load: 32 cols x 8-row strides

    float acc[4][4] = {};

    for (int nt = 0; nt < LSEQ / NSPLIT; nt += 32) {
#pragma unroll
        for (int i = 0; i < 8; i++) {
            Ks[lr + i * 8][ln] = Kp[(long)(lr + i * 8) * LSEQ + n0 + nt + ln];
            Vs[lr + i * 8][ln] = Vp[(long)(lr + i * 8) * LSEQ + n0 + nt + ln];
        }
        __syncthreads();
#pragma unroll
        for (int n = 0; n < 32; n++) {
            float a[4], bb[4];
#pragma unroll
            for (int i = 0; i < 4; i++) a[i] = Ks[ty * 4 + i][n];
#pragma unroll
            for (int j = 0; j < 4; j++) bb[j] = Vs[tx * 4 + j][n];
#pragma unroll
            for (int i = 0; i < 4; i++)
#pragma unroll
                for (int j = 0; j < 4; j++)
                    acc[i][j] = fmaf(a[i], bb[j], acc[i][j]);
        }
        __syncthreads();
    }

    float* cp = g_ctxp + ((long)bh * NSPLIT + split) * DH * DH;
#pragma unroll
    for (int i = 0; i < 4; i++)
#pragma unroll
        for (int j = 0; j < 4; j++)
            cp[(ty * 4 + i) * DH + tx * 4 + j] = acc[i][j];
}

__global__ __launch_bounds__(256) void ctx_reduce()
{
    const int idx = blockIdx.x * 256 + threadIdx.x;   // 0 .. 64*4096-1
    const int bh = idx >> 12;
    const int i  = idx & 4095;
    float s = 0.0f;
#pragma unroll
    for (int sp = 0; sp < NSPLIT; sp++)
        s += g_ctxp[((long)bh * NSPLIT + sp) * DH * DH + i];
    g_ctx[(long)bh * DH * DH + i] = s;
}

// ---------------------------------------------------------------------------
// Fold w_out into ctx:  WctxT[b][h*64+d][c] = SCALE * sum_e ctx[b,h][d,e]*w_out[h*64+e][c]
// One block per (b,h). w_out column cached in registers (64 floats).
// ---------------------------------------------------------------------------
__global__ __launch_bounds__(256) void wctx_fold(const float* __restrict__ w_out)
{
    const int bh = blockIdx.x;
    const int b = bh / HEADS, h = bh % HEADS;
    __shared__ float cs[64][65];
    const int tid = threadIdx.x;

    const float* cp = g_ctx + (long)bh * DH * DH;
    for (int i = tid; i < DH * DH; i += 256) cs[i >> 6][i & 63] = cp[i];
    __syncthreads();

    float* outp = g_wctxT + (long)b * DIM * DIM + (long)(h * DH) * DIM;

    for (int cb = 0; cb < 2; cb++) {
        const int c = cb * 256 + tid;
        float w[64];
#pragma unroll
        for (int e = 0; e < 64; e++) w[e] = w_out[(h * DH + e) * DIM + c];
#pragma unroll 4
        for (int d = 0; d < 64; d++) {
            float s = 0.0f;
#pragma unroll
            for (int e = 0; e < 64; e++) s = fmaf(cs[d][e], w[e], s);
            outp[(long)d * DIM + c] = s * SCALE;
        }
    }
}

// ---------------------------------------------------------------------------
extern "C" void kernel_launch(void* const* d_in, const int* in_sizes, int n_in,
                              void* d_out, int out_size)
{
    const float* x      = (const float*)d_in[0];   // (B, 512, 4096)
    const float* w_qkv  = (const float*)d_in[1];   // (512, 1536)
    const float* w_out  = (const float*)d_in[2];   // (512, 512)
    const float* b_out  = (const float*)d_in[3];   // (512,)
    float* out = (float*)d_out;                    // (B, 512, 4096)

    float* qkv;
    float* wctxT;
    cudaGetSymbolAddress((void**)&qkv,   g_qkv);
    cudaGetSymbolAddress((void**)&wctxT, g_wctxT);

    // 1) QKV = W^T @ X per batch: A = w_qkv (K=512 x M=1536), B = x (512 x 4096)
    {
        dim3 grid(LSEQ / 64, F3 / 64, BATCH);
        gemm_kkm<<<grid, 256>>>(w_qkv, x, qkv,
                                F3, LSEQ, DIM, F3, LSEQ, LSEQ,
                                0L, (long)DIM * LSEQ, (long)F3 * LSEQ,
                                nullptr);
    }

    // 2) softmax over L on the K third (in place)
    softmax_rows<<<BATCH * DIM, 256>>>();

    // 3) ctx partials + reduce
    {
        dim3 grid(BATCH * HEADS, NSPLIT);
        ctx_partial<<<grid, 256>>>();
        ctx_reduce<<<(BATCH * HEADS * DH * DH) / 256, 256>>>();
    }

    // 4) fold w_out into ctx (includes SCALE)
    wctx_fold<<<BATCH * HEADS, 256>>>(w_out);

    // 5) out = WctxT^T @ q + bias: A = wctxT (K=512 x M=512), B = q rows of qkv
    {
        dim3 grid(LSEQ / 64, DIM / 64, BATCH);
        gemm_kkm<<<grid, 256>>>(wctxT, qkv, out,
                                DIM, LSEQ, DIM, DIM, LSEQ, LSEQ,
                                (long)DIM * DIM, (long)F3 * LSEQ, (long)DIM * LSEQ,
                                b_out);
    }
}

// round 2
// speedup vs baseline: 2.6008x; 2.6008x over previous
#include <cuda_runtime.h>
#include <math.h>
#include <stdint.h>

#define BATCH 8
#define DIM   512
#define HEADS 8
#define DH    64
#define LSEQ  4096
#define F3    1536            // 3 * HEADS * DH
#define SCALE 0.125f          // DH^-0.5
#define NSPLIT 16

// ---------------- scratch (device globals; no allocation allowed) ----------
__device__ float g_qkv[(size_t)BATCH * F3 * LSEQ];                  // 201 MB
__device__ float g_ctxp[(size_t)BATCH * HEADS * NSPLIT * DH * DH];  // 16.8 MB
__device__ float g_ctx[(size_t)BATCH * HEADS * DH * DH];            // 1 MB
__device__ float g_wctxT[(size_t)BATCH * DIM * DIM];                // 8 MB

// ---------------------------------------------------------------------------
// Tensor-core GEMM (tf32 mma.sync):  C[m,n] = sum_k A[k,m]*B[k,n] (+bias[m])
// A: K-major (K x M, row stride lda); B: K-major (K x N, row stride ldb).
// BM=BN=128, BK=16, 256 threads (8 warps in 2x4), warp tile 64x32 via
// 4x4 grid of m16n8k8. Operands pre-rounded to tf32 (RN) at staging so the
// HW truncation is exact -> unbiased rounding error.
// ---------------------------------------------------------------------------
#define BM 128
#define BN 128
#define BK 16

__device__ __forceinline__ uint32_t f2tf32(float x) {
    uint32_t u;
    asm("cvt.rna.tf32.f32 %0, %1;" : "=r"(u) : "f"(x));
    return u;
}

__device__ __forceinline__ void mma_tf32(float c[4], const uint32_t a[4], const uint32_t b[2]) {
    asm volatile(
        "mma.sync.aligned.m16n8k8.row.col.f32.tf32.tf32.f32 "
        "{%0,%1,%2,%3}, {%4,%5,%6,%7}, {%8,%9}, {%0,%1,%2,%3};"
        : "+f"(c[0]), "+f"(c[1]), "+f"(c[2]), "+f"(c[3])
        : "r"(a[0]), "r"(a[1]), "r"(a[2]), "r"(a[3]), "r"(b[0]), "r"(b[1]));
}

__global__ __launch_bounds__(256, 2) void gemm_tf32(
    const float* __restrict__ A, const float* __restrict__ B,
    float* __restrict__ C,
    int lda, int ldb, int ldc, int K,
    long sA, long sB, long sC,
    const float* __restrict__ bias)
{
    A += (long)blockIdx.z * sA;
    B += (long)blockIdx.z * sB;
    C += (long)blockIdx.z * sC;

    const int m0 = blockIdx.y * BM;
    const int n0 = blockIdx.x * BN;

    __shared__ uint32_t As[2][BK][BM + 4];
    __shared__ uint32_t Bs[2][BK][BN + 4];

    const int tid  = threadIdx.x;
    const int lane = tid & 31;
    const int g    = lane >> 2;        // group id (row within 16/8 tile)
    const int tg   = lane & 3;         // thread-in-group (k index)
    const int warp = tid >> 5;
    const int wm   = (warp >> 2) * 64; // warp m offset (2 rows of warps)
    const int wn   = (warp & 3) * 32;  // warp n offset (4 cols of warps)

    // staging: 2 float4 per thread per operand tile
    const int srow0 = tid >> 5;              // rows 0..7  (idx = tid)
    const int scol0 = (tid & 31) * 4;
    const int srow1 = 8 + (tid >> 5);        // rows 8..15 (idx = tid+256)
    const int scol1 = scol0;

    float c[4][4][4];
#pragma unroll
    for (int i = 0; i < 4; i++)
#pragma unroll
        for (int j = 0; j < 4; j++)
#pragma unroll
            for (int q = 0; q < 4; q++) c[i][j][q] = 0.0f;

    const int ntiles = K / BK;

    float4 pa0, pa1, pb0, pb1;

    // prefetch tile 0
    pa0 = *reinterpret_cast<const float4*>(&A[(long)srow0 * lda + m0 + scol0]);
    pa1 = *reinterpret_cast<const float4*>(&A[(long)srow1 * lda + m0 + scol1]);
    pb0 = *reinterpret_cast<const float4*>(&B[(long)srow0 * ldb + n0 + scol0]);
    pb1 = *reinterpret_cast<const float4*>(&B[(long)srow1 * ldb + n0 + scol1]);

    int buf = 0;
    {
        uint4 ua0 = {f2tf32(pa0.x), f2tf32(pa0.y), f2tf32(pa0.z), f2tf32(pa0.w)};
        uint4 ua1 = {f2tf32(pa1.x), f2tf32(pa1.y), f2tf32(pa1.z), f2tf32(pa1.w)};
        uint4 ub0 = {f2tf32(pb0.x), f2tf32(pb0.y), f2tf32(pb0.z), f2tf32(pb0.w)};
        uint4 ub1 = {f2tf32(pb1.x), f2tf32(pb1.y), f2tf32(pb1.z), f2tf32(pb1.w)};
        *reinterpret_cast<uint4*>(&As[0][srow0][scol0]) = ua0;
        *reinterpret_cast<uint4*>(&As[0][srow1][scol1]) = ua1;
        *reinterpret_cast<uint4*>(&Bs[0][srow0][scol0]) = ub0;
        *reinterpret_cast<uint4*>(&Bs[0][srow1][scol1]) = ub1;
    }
    __syncthreads();

    for (int kt = 0; kt < ntiles; kt++) {
        const bool has_next = (kt + 1) < ntiles;
        if (has_next) {
            const long kb = (long)(kt + 1) * BK;
            pa0 = *reinterpret_cast<const float4*>(&A[(kb + srow0) * lda + m0 + scol0]);
            pa1 = *reinterpret_cast<const float4*>(&A[(kb + srow1) * lda + m0 + scol1]);
            pb0 = *reinterpret_cast<const float4*>(&B[(kb + srow0) * ldb + n0 + scol0]);
            pb1 = *reinterpret_cast<const float4*>(&B[(kb + srow1) * ldb + n0 + scol1]);
        }

#pragma unroll
        for (int ks = 0; ks < BK; ks += 8) {
            uint32_t af[4][4];
            uint32_t bf[4][2];
#pragma unroll
            for (int mt = 0; mt < 4; mt++) {
                const int mb = wm + mt * 16;
                af[mt][0] = As[buf][ks + tg    ][mb + g];
                af[mt][1] = As[buf][ks + tg    ][mb + g + 8];
                af[mt][2] = As[buf][ks + tg + 4][mb + g];
                af[mt][3] = As[buf][ks + tg + 4][mb + g + 8];
            }
#pragma unroll
            for (int nt = 0; nt < 4; nt++) {
                const int nb = wn + nt * 8;
                bf[nt][0] = Bs[buf][ks + tg    ][nb + g];
                bf[nt][1] = Bs[buf][ks + tg + 4][nb + g];
            }
#pragma unroll
            for (int mt = 0; mt < 4; mt++)
#pragma unroll
                for (int nt = 0; nt < 4; nt++)
                    mma_tf32(c[mt][nt], af[mt], bf[nt]);
        }

        if (has_next) {
            uint4 ua0 = {f2tf32(pa0.x), f2tf32(pa0.y), f2tf32(pa0.z), f2tf32(pa0.w)};
            uint4 ua1 = {f2tf32(pa1.x), f2tf32(pa1.y), f2tf32(pa1.z), f2tf32(pa1.w)};
            uint4 ub0 = {f2tf32(pb0.x), f2tf32(pb0.y), f2tf32(pb0.z), f2tf32(pb0.w)};
            uint4 ub1 = {f2tf32(pb1.x), f2tf32(pb1.y), f2tf32(pb1.z), f2tf32(pb1.w)};
            const int nb = buf ^ 1;
            *reinterpret_cast<uint4*>(&As[nb][srow0][scol0]) = ua0;
            *reinterpret_cast<uint4*>(&As[nb][srow1][scol1]) = ua1;
            *reinterpret_cast<uint4*>(&Bs[nb][srow0][scol0]) = ub0;
            *reinterpret_cast<uint4*>(&Bs[nb][srow1][scol1]) = ub1;
        }
        __syncthreads();
        buf ^= 1;
    }

    // epilogue
#pragma unroll
    for (int mt = 0; mt < 4; mt++) {
        const int m = m0 + wm + mt * 16 + g;
        const float bv0 = bias ? bias[m]     : 0.0f;
        const float bv8 = bias ? bias[m + 8] : 0.0f;
#pragma unroll
        for (int nt = 0; nt < 4; nt++) {
            const int n = n0 + wn + nt * 8 + 2 * tg;
            float2 o0 = {c[mt][nt][0] + bv0, c[mt][nt][1] + bv0};
            float2 o1 = {c[mt][nt][2] + bv8, c[mt][nt][3] + bv8};
            *reinterpret_cast<float2*>(&C[(long)m * ldc + n])       = o0;
            *reinterpret_cast<float2*>(&C[(long)(m + 8) * ldc + n]) = o1;
        }
    }
}

// ---------------------------------------------------------------------------
// Softmax over L for the K third of qkv (rows [DIM, 2*DIM) per batch), in place.
// ---------------------------------------------------------------------------
__global__ __launch_bounds__(256) void softmax_rows()
{
    const int row = blockIdx.x;           // 0 .. BATCH*DIM-1
    const int b = row / DIM;
    const int r = row % DIM;
    float* p = g_qkv + (long)b * F3 * LSEQ + (long)(DIM + r) * LSEQ;

    const int tid = threadIdx.x;
    float4 v[4];
    float mx = -1e30f;
#pragma unroll
    for (int i = 0; i < 4; i++) {
        v[i] = reinterpret_cast<float4*>(p)[tid + i * 256];
        mx = fmaxf(mx, fmaxf(fmaxf(v[i].x, v[i].y), fmaxf(v[i].z, v[i].w)));
    }

    __shared__ float red[8];
#pragma unroll
    for (int o = 16; o; o >>= 1) mx = fmaxf(mx, __shfl_xor_sync(~0u, mx, o));
    if ((tid & 31) == 0) red[tid >> 5] = mx;
    __syncthreads();
    mx = red[0];
#pragma unroll
    for (int i = 1; i < 8; i++) mx = fmaxf(mx, red[i]);
    __syncthreads();

    float s = 0.0f;
#pragma unroll
    for (int i = 0; i < 4; i++) {
        v[i].x = expf(v[i].x - mx);
        v[i].y = expf(v[i].y - mx);
        v[i].z = expf(v[i].z - mx);
        v[i].w = expf(v[i].w - mx);
        s += v[i].x + v[i].y + v[i].z + v[i].w;
    }
#pragma unroll
    for (int o = 16; o; o >>= 1) s += __shfl_xor_sync(~0u, s, o);
    if ((tid & 31) == 0) red[tid >> 5] = s;
    __syncthreads();
    s = red[0];
#pragma unroll
    for (int i = 1; i < 8; i++) s += red[i];
    const float inv = 1.0f / s;

#pragma unroll
    for (int i = 0; i < 4; i++) {
        v[i].x *= inv; v[i].y *= inv; v[i].z *= inv; v[i].w *= inv;
        reinterpret_cast<float4*>(p)[tid + i * 256] = v[i];
    }
}

// ---------------------------------------------------------------------------
// ctx partials: per (b,h,split): partial[d,e] = sum_{n in slice} Ksm[d,n]*V[e,n]
// ---------------------------------------------------------------------------
__global__ __launch_bounds__(256) void ctx_partial()
{
    const int bh = blockIdx.x;                 // 0..63
    const int split = blockIdx.y;              // 0..NSPLIT-1
    const int b = bh / HEADS, h = bh % HEADS;
    const float* Kp = g_qkv + (long)b * F3 * LSEQ + (long)(DIM + h * DH) * LSEQ;
    const float* Vp = g_qkv + (long)b * F3 * LSEQ + (long)(2 * DIM + h * DH) * LSEQ;
    const int n0 = split * (LSEQ / NSPLIT);    // 256 per slice

    __shared__ float Ks[64][33];
    __shared__ float Vs[64][33];

    const int tid = threadIdx.x;
    const int tx = tid & 15, ty = tid >> 4;
    const int ln = tid & 31, lr = tid >> 5;    // load: 32 cols x 8-row strides

    float acc[4][4] = {};

    for (int nt = 0; nt < LSEQ / NSPLIT; nt += 32) {
#pragma unroll
        for (int i = 0; i < 8; i++) {
            Ks[lr + i * 8][ln] = Kp[(long)(lr + i * 8) * LSEQ + n0 + nt + ln];
            Vs[lr + i * 8][ln] = Vp[(long)(lr + i * 8) * LSEQ + n0 + nt + ln];
        }
        __syncthreads();
#pragma unroll
        for (int n = 0; n < 32; n++) {
            float a[4], bb[4];
#pragma unroll
            for (int i = 0; i < 4; i++) a[i] = Ks[ty * 4 + i][n];
#pragma unroll
            for (int j = 0; j < 4; j++) bb[j] = Vs[tx * 4 + j][n];
#pragma unroll
            for (int i = 0; i < 4; i++)
#pragma unroll
                for (int j = 0; j < 4; j++)
                    acc[i][j] = fmaf(a[i], bb[j], acc[i][j]);
        }
        __syncthreads();
    }

    float* cp = g_ctxp + ((long)bh * NSPLIT + split) * DH * DH;
#pragma unroll
    for (int i = 0; i < 4; i++)
#pragma unroll
        for (int j = 0; j < 4; j++)
            cp[(ty * 4 + i) * DH + tx * 4 + j] = acc[i][j];
}

__global__ __launch_bounds__(256) void ctx_reduce()
{
    const int idx = blockIdx.x * 256 + threadIdx.x;   // 0 .. 64*4096-1
    const int bh = idx >> 12;
    const int i  = idx & 4095;
    float s = 0.0f;
#pragma unroll
    for (int sp = 0; sp < NSPLIT; sp++)
        s += g_ctxp[((long)bh * NSPLIT + sp) * DH * DH + i];
    g_ctx[(long)bh * DH * DH + i] = s;
}

// ---------------------------------------------------------------------------
// Fold w_out into ctx:  WctxT[b][h*64+d][c] = SCALE * sum_e ctx[b,h][d,e]*w_out[h*64+e][c]
// ---------------------------------------------------------------------------
__global__ __launch_bounds__(256) void wctx_fold(const float* __restrict__ w_out)
{
    const int bh = blockIdx.x;
    const int b = bh / HEADS, h = bh % HEADS;
    __shared__ float cs[64][65];
    const int tid = threadIdx.x;

    const float* cp = g_ctx + (long)bh * DH * DH;
    for (int i = tid; i < DH * DH; i += 256) cs[i >> 6][i & 63] = cp[i];
    __syncthreads();

    float* outp = g_wctxT + (long)b * DIM * DIM + (long)(h * DH) * DIM;

    for (int cb = 0; cb < 2; cb++) {
        const int c = cb * 256 + tid;
        float w[64];
#pragma unroll
        for (int e = 0; e < 64; e++) w[e] = w_out[(h * DH + e) * DIM + c];
#pragma unroll 4
        for (int d = 0; d < 64; d++) {
            float s = 0.0f;
#pragma unroll
            for (int e = 0; e < 64; e++) s = fmaf(cs[d][e], w[e], s);
            outp[(long)d * DIM + c] = s * SCALE;
        }
    }
}

// ---------------------------------------------------------------------------
extern "C" void kernel_launch(void* const* d_in, const int* in_sizes, int n_in,
                              void* d_out, int out_size)
{
    const float* x      = (const float*)d_in[0];   // (B, 512, 4096)
    const float* w_qkv  = (const float*)d_in[1];   // (512, 1536)
    const float* w_out  = (const float*)d_in[2];   // (512, 512)
    const float* b_out  = (const float*)d_in[3];   // (512,)
    float* out = (float*)d_out;                    // (B, 512, 4096)

    float* qkv;
    float* wctxT;
    cudaGetSymbolAddress((void**)&qkv,   g_qkv);
    cudaGetSymbolAddress((void**)&wctxT, g_wctxT);

    // 1) QKV = W^T @ X per batch (tensor cores, tf32)
    {
        dim3 grid(LSEQ / BN, F3 / BM, BATCH);
        gemm_tf32<<<grid, 256>>>(w_qkv, x, qkv,
                                 F3, LSEQ, LSEQ, DIM,
                                 0L, (long)DIM * LSEQ, (long)F3 * LSEQ,
                                 nullptr);
    }

    // 2) softmax over L on the K third (in place)
    softmax_rows<<<BATCH * DIM, 256>>>();

    // 3) ctx partials + reduce
    {
        dim3 grid(BATCH * HEADS, NSPLIT);
        ctx_partial<<<grid, 256>>>();
        ctx_reduce<<<(BATCH * HEADS * DH * DH) / 256, 256>>>();
    }

    // 4) fold w_out into ctx (includes SCALE)
    wctx_fold<<<BATCH * HEADS, 256>>>(w_out);

    // 5) out = WctxT^T @ q + bias (tensor cores, tf32)
    {
        dim3 grid(LSEQ / BN, DIM / BM, BATCH);
        gemm_tf32<<<grid, 256>>>(wctxT, qkv, out,
                                 DIM, LSEQ, LSEQ, DIM,
                                 (long)DIM * DIM, (long)F3 * LSEQ, (long)DIM * LSEQ,
                                 b_out);
    }
}

// round 4
// speedup vs baseline: 3.0503x; 1.1728x over previous
#include <cuda_runtime.h>
#include <math.h>
#include <stdint.h>

#define BATCH 8
#define DIM   512
#define HEADS 8
#define DH    64
#define LSEQ  4096
#define F3    1536            // 3 * HEADS * DH
#define FKV   1024            // k,v thirds only
#define SCALE 0.125f          // DH^-0.5
#define NSPLIT 16

// ---------------- scratch (device globals; no allocation allowed) ----------
__device__ float g_qkv[(size_t)BATCH * FKV * LSEQ];                 // 134 MB (k,v only)
__device__ float g_ctxp[(size_t)BATCH * HEADS * NSPLIT * DH * DH];  // 16.8 MB
__device__ float g_ctx[(size_t)BATCH * HEADS * DH * DH];            // 1 MB
__device__ float g_wctxT[(size_t)BATCH * DIM * DIM];                // 8 MB
__device__ float g_wqT[(size_t)DIM * DIM];                          // 1 MB
__device__ float g_M2[(size_t)BATCH * DIM * DIM];                   // 8 MB

// ======================= helpers ==========================================
__device__ __forceinline__ uint32_t f2tf32(float x) {
    uint32_t u;
    asm("cvt.rna.tf32.f32 %0, %1;" : "=r"(u) : "f"(x));
    return u;
}

// ======================= transpose ========================================
// out[c][r] = in[r*ldin + c]; in has R rows, we transpose a RxC block.
__global__ __launch_bounds__(256) void transpose_k(
    const float* __restrict__ in, float* __restrict__ out,
    int R, int C, int ldin)
{
    __shared__ float t[32][33];
    const int c0 = blockIdx.x * 32;
    const int r0 = blockIdx.y * 32;
    const int tx = threadIdx.x & 31;
    const int ty = threadIdx.x >> 5;   // 0..7
#pragma unroll
    for (int i = 0; i < 4; i++)
        t[ty + i * 8][tx] = in[(long)(r0 + ty + i * 8) * ldin + c0 + tx];
    __syncthreads();
#pragma unroll
    for (int i = 0; i < 4; i++)
        out[(long)(c0 + ty + i * 8) * R + r0 + tx] = t[tx][ty + i * 8];
}

// ======================= tf32 warp-MMA GEMM ================================
// C[m,n] = sum_k A[k,m]*B[k,n] (+bias[m]); A: KxM (lda), B: KxN (ldb).
#define BM 128
#define BN 128
#define BK 16

__device__ __forceinline__ void mma_tf32(float c[4], const uint32_t a[4], const uint32_t b[2]) {
    asm volatile(
        "mma.sync.aligned.m16n8k8.row.col.f32.tf32.tf32.f32 "
        "{%0,%1,%2,%3}, {%4,%5,%6,%7}, {%8,%9}, {%0,%1,%2,%3};"
        : "+f"(c[0]), "+f"(c[1]), "+f"(c[2]), "+f"(c[3])
        : "r"(a[0]), "r"(a[1]), "r"(a[2]), "r"(a[3]), "r"(b[0]), "r"(b[1]));
}

__global__ __launch_bounds__(256, 2) void gemm_tf32(
    const float* __restrict__ A, const float* __restrict__ B,
    float* __restrict__ C,
    int lda, int ldb, int ldc, int K,
    long sA, long sB, long sC,
    const float* __restrict__ bias)
{
    A += (long)blockIdx.z * sA;
    B += (long)blockIdx.z * sB;
    C += (long)blockIdx.z * sC;

    const int m0 = blockIdx.y * BM;
    const int n0 = blockIdx.x * BN;

    __shared__ uint32_t As[2][BK][BM + 4];
    __shared__ uint32_t Bs[2][BK][BN + 4];

    const int tid  = threadIdx.x;
    const int lane = tid & 31;
    const int g    = lane >> 2;
    const int tg   = lane & 3;
    const int warp = tid >> 5;
    const int wm   = (warp >> 2) * 64;
    const int wn   = (warp & 3) * 32;

    const int srow0 = tid >> 5;
    const int scol0 = (tid & 31) * 4;
    const int srow1 = 8 + (tid >> 5);
    const int scol1 = scol0;

    float c[4][4][4];
#pragma unroll
    for (int i = 0; i < 4; i++)
#pragma unroll
        for (int j = 0; j < 4; j++)
#pragma unroll
            for (int q = 0; q < 4; q++) c[i][j][q] = 0.0f;

    const int ntiles = K / BK;
    float4 pa0, pa1, pb0, pb1;

    pa0 = *reinterpret_cast<const float4*>(&A[(long)srow0 * lda + m0 + scol0]);
    pa1 = *reinterpret_cast<const float4*>(&A[(long)srow1 * lda + m0 + scol1]);
    pb0 = *reinterpret_cast<const float4*>(&B[(long)srow0 * ldb + n0 + scol0]);
    pb1 = *reinterpret_cast<const float4*>(&B[(long)srow1 * ldb + n0 + scol1]);

    int buf = 0;
    {
        uint4 ua0 = {f2tf32(pa0.x), f2tf32(pa0.y), f2tf32(pa0.z), f2tf32(pa0.w)};
        uint4 ua1 = {f2tf32(pa1.x), f2tf32(pa1.y), f2tf32(pa1.z), f2tf32(pa1.w)};
        uint4 ub0 = {f2tf32(pb0.x), f2tf32(pb0.y), f2tf32(pb0.z), f2tf32(pb0.w)};
        uint4 ub1 = {f2tf32(pb1.x), f2tf32(pb1.y), f2tf32(pb1.z), f2tf32(pb1.w)};
        *reinterpret_cast<uint4*>(&As[0][srow0][scol0]) = ua0;
        *reinterpret_cast<uint4*>(&As[0][srow1][scol1]) = ua1;
        *reinterpret_cast<uint4*>(&Bs[0][srow0][scol0]) = ub0;
        *reinterpret_cast<uint4*>(&Bs[0][srow1][scol1]) = ub1;
    }
    __syncthreads();

    for (int kt = 0; kt < ntiles; kt++) {
        const bool has_next = (kt + 1) < ntiles;
        if (has_next) {
            const long kb = (long)(kt + 1) * BK;
            pa0 = *reinterpret_cast<const float4*>(&A[(kb + srow0) * lda + m0 + scol0]);
            pa1 = *reinterpret_cast<const float4*>(&A[(kb + srow1) * lda + m0 + scol1]);
            pb0 = *reinterpret_cast<const float4*>(&B[(kb + srow0) * ldb + n0 + scol0]);
            pb1 = *reinterpret_cast<const float4*>(&B[(kb + srow1) * ldb + n0 + scol1]);
        }

#pragma unroll
        for (int ks = 0; ks < BK; ks += 8) {
            uint32_t af[4][4];
            uint32_t bf[4][2];
#pragma unroll
            for (int mt = 0; mt < 4; mt++) {
                const int mb = wm + mt * 16;
                af[mt][0] = As[buf][ks + tg    ][mb + g];
                af[mt][1] = As[buf][ks + tg    ][mb + g + 8];
                af[mt][2] = As[buf][ks + tg + 4][mb + g];
                af[mt][3] = As[buf][ks + tg + 4][mb + g + 8];
            }
#pragma unroll
            for (int nt = 0; nt < 4; nt++) {
                const int nb = wn + nt * 8;
                bf[nt][0] = Bs[buf][ks + tg    ][nb + g];
                bf[nt][1] = Bs[buf][ks + tg + 4][nb + g];
            }
#pragma unroll
            for (int mt = 0; mt < 4; mt++)
#pragma unroll
                for (int nt = 0; nt < 4; nt++)
                    mma_tf32(c[mt][nt], af[mt], bf[nt]);
        }

        if (has_next) {
            uint4 ua0 = {f2tf32(pa0.x), f2tf32(pa0.y), f2tf32(pa0.z), f2tf32(pa0.w)};
            uint4 ua1 = {f2tf32(pa1.x), f2tf32(pa1.y), f2tf32(pa1.z), f2tf32(pa1.w)};
            uint4 ub0 = {f2tf32(pb0.x), f2tf32(pb0.y), f2tf32(pb0.z), f2tf32(pb0.w)};
            uint4 ub1 = {f2tf32(pb1.x), f2tf32(pb1.y), f2tf32(pb1.z), f2tf32(pb1.w)};
            const int nb = buf ^ 1;
            *reinterpret_cast<uint4*>(&As[nb][srow0][scol0]) = ua0;
            *reinterpret_cast<uint4*>(&As[nb][srow1][scol1]) = ua1;
            *reinterpret_cast<uint4*>(&Bs[nb][srow0][scol0]) = ub0;
            *reinterpret_cast<uint4*>(&Bs[nb][srow1][scol1]) = ub1;
        }
        __syncthreads();
        buf ^= 1;
    }

#pragma unroll
    for (int mt = 0; mt < 4; mt++) {
        const int m = m0 + wm + mt * 16 + g;
        const float bv0 = bias ? bias[m]     : 0.0f;
        const float bv8 = bias ? bias[m + 8] : 0.0f;
#pragma unroll
        for (int nt = 0; nt < 4; nt++) {
            const int n = n0 + wn + nt * 8 + 2 * tg;
            float2 o0 = {c[mt][nt][0] + bv0, c[mt][nt][1] + bv0};
            float2 o1 = {c[mt][nt][2] + bv8, c[mt][nt][3] + bv8};
            *reinterpret_cast<float2*>(&C[(long)m * ldc + n])       = o0;
            *reinterpret_cast<float2*>(&C[(long)(m + 8) * ldc + n]) = o1;
        }
    }
}

// ======================= softmax over L (k third, in place) ================
// k rows now live at rows [0, DIM) of g_qkv (per-batch stride FKV*LSEQ).
__global__ __launch_bounds__(256) void softmax_rows()
{
    const int row = blockIdx.x;           // 0 .. BATCH*DIM-1
    const int b = row / DIM;
    const int r = row % DIM;
    float* p = g_qkv + (long)b * FKV * LSEQ + (long)r * LSEQ;

    const int tid = threadIdx.x;
    float4 v[4];
    float mx = -1e30f;
#pragma unroll
    for (int i = 0; i < 4; i++) {
        v[i] = reinterpret_cast<float4*>(p)[tid + i * 256];
        mx = fmaxf(mx, fmaxf(fmaxf(v[i].x, v[i].y), fmaxf(v[i].z, v[i].w)));
    }

    __shared__ float red[8];
#pragma unroll
    for (int o = 16; o; o >>= 1) mx = fmaxf(mx, __shfl_xor_sync(~0u, mx, o));
    if ((tid & 31) == 0) red[tid >> 5] = mx;
    __syncthreads();
    mx = red[0];
#pragma unroll
    for (int i = 1; i < 8; i++) mx = fmaxf(mx, red[i]);
    __syncthreads();

    float s = 0.0f;
#pragma unroll
    for (int i = 0; i < 4; i++) {
        v[i].x = expf(v[i].x - mx);
        v[i].y = expf(v[i].y - mx);
        v[i].z = expf(v[i].z - mx);
        v[i].w = expf(v[i].w - mx);
        s += v[i].x + v[i].y + v[i].z + v[i].w;
    }
#pragma unroll
    for (int o = 16; o; o >>= 1) s += __shfl_xor_sync(~0u, s, o);
    if ((tid & 31) == 0) red[tid >> 5] = s;
    __syncthreads();
    s = red[0];
#pragma unroll
    for (int i = 1; i < 8; i++) s += red[i];
    const float inv = 1.0f / s;

#pragma unroll
    for (int i = 0; i < 4; i++) {
        v[i].x *= inv; v[i].y *= inv; v[i].z *= inv; v[i].w *= inv;
        reinterpret_cast<float4*>(p)[tid + i * 256] = v[i];
    }
}

// ======================= ctx partials + reduce =============================
__global__ __launch_bounds__(256) void ctx_partial()
{
    const int bh = blockIdx.x;                 // 0..63
    const int split = blockIdx.y;              // 0..NSPLIT-1
    const int b = bh / HEADS, h = bh % HEADS;
    const float* Kp = g_qkv + (long)b * FKV * LSEQ + (long)(h * DH) * LSEQ;
    const float* Vp = g_qkv + (long)b * FKV * LSEQ + (long)(DIM + h * DH) * LSEQ;
    const int n0 = split * (LSEQ / NSPLIT);

    __shared__ float Ks[64][33];
    __shared__ float Vs[64][33];

    const int tid = threadIdx.x;
    const int tx = tid & 15, ty = tid >> 4;
    const int ln = tid & 31, lr = tid >> 5;

    float acc[4][4] = {};

    for (int nt = 0; nt < LSEQ / NSPLIT; nt += 32) {
#pragma unroll
        for (int i = 0; i < 8; i++) {
            Ks[lr + i * 8][ln] = Kp[(long)(lr + i * 8) * LSEQ + n0 + nt + ln];
            Vs[lr + i * 8][ln] = Vp[(long)(lr + i * 8) * LSEQ + n0 + nt + ln];
        }
        __syncthreads();
#pragma unroll
        for (int n = 0; n < 32; n++) {
            float a[4], bb[4];
#pragma unroll
            for (int i = 0; i < 4; i++) a[i] = Ks[ty * 4 + i][n];
#pragma unroll
            for (int j = 0; j < 4; j++) bb[j] = Vs[tx * 4 + j][n];
#pragma unroll
            for (int i = 0; i < 4; i++)
#pragma unroll
                for (int j = 0; j < 4; j++)
                    acc[i][j] = fmaf(a[i], bb[j], acc[i][j]);
        }
        __syncthreads();
    }

    float* cp = g_ctxp + ((long)bh * NSPLIT + split) * DH * DH;
#pragma unroll
    for (int i = 0; i < 4; i++)
#pragma unroll
        for (int j = 0; j < 4; j++)
            cp[(ty * 4 + i) * DH + tx * 4 + j] = acc[i][j];
}

__global__ __launch_bounds__(256) void ctx_reduce()
{
    const int idx = blockIdx.x * 256 + threadIdx.x;
    const int bh = idx >> 12;
    const int i  = idx & 4095;
    float s = 0.0f;
#pragma unroll
    for (int sp = 0; sp < NSPLIT; sp++)
        s += g_ctxp[((long)bh * NSPLIT + sp) * DH * DH + i];
    g_ctx[(long)bh * DH * DH + i] = s;
}

// ======================= fold w_out into ctx ===============================
// WctxT[b][(h,d)][c] = SCALE * sum_e ctx[b,h][d,e]*w_out[h*64+e][c]
__global__ __launch_bounds__(256) void wctx_fold(const float* __restrict__ w_out)
{
    const int bh = blockIdx.x;
    const int b = bh / HEADS, h = bh % HEADS;
    __shared__ float cs[64][65];
    const int tid = threadIdx.x;

    const float* cp = g_ctx + (long)bh * DH * DH;
    for (int i = tid; i < DH * DH; i += 256) cs[i >> 6][i & 63] = cp[i];
    __syncthreads();

    float* outp = g_wctxT + (long)b * DIM * DIM + (long)(h * DH) * DIM;

    for (int cb = 0; cb < 2; cb++) {
        const int c = cb * 256 + tid;
        float w[64];
#pragma unroll
        for (int e = 0; e < 64; e++) w[e] = w_out[(h * DH + e) * DIM + c];
#pragma unroll 4
        for (int d = 0; d < 64; d++) {
            float s = 0.0f;
#pragma unroll
            for (int e = 0; e < 64; e++) s = fmaf(cs[d][e], w[e], s);
            outp[(long)d * DIM + c] = s * SCALE;
        }
    }
}

// ---------------------------------------------------------------------------
extern "C" void kernel_launch(void* const* d_in, const int* in_sizes, int n_in,
                              void* d_out, int out_size)
{
    const float* x      = (const float*)d_in[0];   // (B, 512, 4096)
    const float* w_qkv  = (const float*)d_in[1];   // (512, 1536)
    const float* w_out  = (const float*)d_in[2];   // (512, 512)
    const float* b_out  = (const float*)d_in[3];   // (512,)
    float* out = (float*)d_out;                    // (B, 512, 4096)

    float* qkv;
    float* wctxT;
    float* wqT;
    float* M2;
    cudaGetSymbolAddress((void**)&qkv,   g_qkv);
    cudaGetSymbolAddress((void**)&wctxT, g_wctxT);
    cudaGetSymbolAddress((void**)&wqT,   g_wqT);
    cudaGetSymbolAddress((void**)&M2,    g_M2);

    // 0) wqT[f][cin] = w_qkv[cin][f] for f in [0,512) (q slice)
    {
        dim3 g(DIM / 32, DIM / 32, 1);
        transpose_k<<<g, 256>>>(w_qkv, wqT, DIM, DIM, F3);
    }

    // 1) k,v = W_kv^T @ x per batch: A = w_qkv cols [512,1536) (K=512 x M=1024)
    {
        dim3 grid(LSEQ / BN, FKV / BM, BATCH);
        gemm_tf32<<<grid, 256>>>(w_qkv + DIM, x, qkv,
                                 F3, LSEQ, LSEQ, DIM,
                                 0L, (long)DIM * LSEQ, (long)FKV * LSEQ,
                                 nullptr);
    }

    // 2) softmax over L on k (in place)
    softmax_rows<<<BATCH * DIM, 256>>>();

    // 3) ctx partials + reduce
    {
        dim3 grid(BATCH * HEADS, NSPLIT);
        ctx_partial<<<grid, 256>>>();
        ctx_reduce<<<(BATCH * HEADS * DH * DH) / 256, 256>>>();
    }

    // 4) fold w_out into ctx (includes SCALE)
    wctx_fold<<<BATCH * HEADS, 256>>>(w_out);

    // 5) M2[b][cin][c] = sum_f wqT[f][cin] * wctxT[b][f][c]   (512^3 per batch)
    {
        dim3 grid(DIM / BN, DIM / BM, BATCH);
        gemm_tf32<<<grid, 256>>>(wqT, wctxT, M2,
                                 DIM, DIM, DIM, DIM,
                                 0L, (long)DIM * DIM, (long)DIM * DIM,
                                 nullptr);
    }

    // 6) out[b][c][l] = sum_cin M2[b][cin][c] * x[b][cin][l] + b_out[c]
    {
        dim3 grid(LSEQ / BN, DIM / BM, BATCH);
        gemm_tf32<<<grid, 256>>>(M2, x, out,
                                 DIM, LSEQ, LSEQ, DIM,
                                 (long)DIM * DIM, (long)DIM * LSEQ, (long)DIM * LSEQ,
                                 b_out);
    }
}